// round 15
// baseline (speedup 1.0000x reference)
#include <cuda_runtime.h>
#include <cuda_bf16.h>
#include <cuda_fp16.h>
#include <math.h>
#include <stdint.h>

// Problem constants
#define TT   4096      // tokens = B*S
#define DD   1024      // model dim
#define HH   1024      // hidden dim
#define EE   16        // experts
#define KK   2         // top-k
#define CAP  640       // capacity
#define CBUF 1280      // K*capacity

// GEMM tiling
#define BM    128      // token rows per block
#define BK    32       // K elements per smem chunk (fp16)
#define NCH   32       // 1024 / 32 chunks
#define ROWB  80       // padded smem row stride bytes (32*2 + 16)

// gemm1 stage (30720 B): Ah@0 (128x80), Al@10240, B@20480 (2 tiles x 5120: gate, up)
#define G1_STG   30720
#define G1_AH    0
#define G1_AL    10240
#define G1_B     20480
// gemm2 stage (15360 B): A@0 (128x80), B@10240 (64x80)
#define G2_STG   15360
#define G2_A     0
#define G2_B     10240

// ---------------- PTX helpers ----------------
__device__ __forceinline__ uint32_t smem_u32(const void* p) {
    uint32_t a;
    asm("{ .reg .u64 t; cvta.to.shared.u64 t, %1; cvt.u32.u64 %0, t; }" : "=r"(a) : "l"(p));
    return a;
}
__device__ __forceinline__ void ldmx4(uint32_t* r, uint32_t a) {
    asm volatile("ldmatrix.sync.aligned.m8n8.x4.shared.b16 {%0,%1,%2,%3}, [%4];"
                 : "=r"(r[0]), "=r"(r[1]), "=r"(r[2]), "=r"(r[3]) : "r"(a));
}
__device__ __forceinline__ void ldmx2(uint32_t* r, uint32_t a) {
    asm volatile("ldmatrix.sync.aligned.m8n8.x2.shared.b16 {%0,%1}, [%2];"
                 : "=r"(r[0]), "=r"(r[1]) : "r"(a));
}
__device__ __forceinline__ void mma_f16(float* c, const uint32_t* a, const uint32_t* b) {
    asm volatile("mma.sync.aligned.m16n8k16.row.col.f32.f16.f16.f32 "
                 "{%0,%1,%2,%3}, {%4,%5,%6,%7}, {%8,%9}, {%0,%1,%2,%3};"
                 : "+f"(c[0]), "+f"(c[1]), "+f"(c[2]), "+f"(c[3])
                 : "r"(a[0]), "r"(a[1]), "r"(a[2]), "r"(a[3]), "r"(b[0]), "r"(b[1]));
}
__device__ __forceinline__ void cp16(uint32_t dst, const void* src, bool pred) {
    int sz = pred ? 16 : 0;
    asm volatile("cp.async.cg.shared.global [%0], [%1], 16, %2;"
                 :: "r"(dst), "l"(src), "r"(sz) : "memory");
}
#define CP_COMMIT() asm volatile("cp.async.commit_group;" ::: "memory")
#define CP_WAIT0()  asm volatile("cp.async.wait_group 0;" ::: "memory")

// ---------------- device scratch ----------------
__device__ int   g_topk_idx[TT * KK];
__device__ float g_topk_w[TT * KK];
__device__ int   g_disp_tok[EE * CBUF];
__device__ float g_disp_w[EE * CBUF];
__device__ int   g_count[EE];

__device__ __align__(16) __half g_xh[(size_t)TT * DD];          // x hi (fp16)
__device__ __align__(16) __half g_xl[(size_t)TT * DD];          // x lo (fp16 residual)
__device__ __align__(16) __half g_gwT[(size_t)EE * HH * DD];    // [E][H][D] fp16
__device__ __align__(16) __half g_uwT[(size_t)EE * HH * DD];
__device__ __align__(16) __half g_dwT[(size_t)EE * DD * HH];    // [E][D][H] fp16
__device__ __align__(16) __half g_hid[(size_t)EE * CBUF * HH];  // hidden (single fp16)

// ---------------- kernel 0: fused prep ----------------
// z in [0,48): transpose+convert weight tensor to fp16 (z>>4: gw/uw/dw, z&15 = e)
// z == 48:     split x into fp16 hi/lo
__global__ void prep_kernel(const float* __restrict__ x,
                            const float* __restrict__ gw,
                            const float* __restrict__ uw,
                            const float* __restrict__ dw) {
    int z = blockIdx.z;
    int tx = threadIdx.x, ty = threadIdx.y;
    if (z < 48) {
        int which = z >> 4;
        int e = z & 15;
        const float* srcw = (which == 0) ? gw : (which == 1) ? uw : dw;
        __half* dst = (which == 0) ? g_gwT : (which == 1) ? g_uwT : g_dwT;

        __shared__ float tile[32][33];
        int r0 = blockIdx.y * 32;
        int c0 = blockIdx.x * 32;
        const float* s = srcw + ((size_t)e * 1024 + r0) * 1024 + c0;
#pragma unroll
        for (int j = 0; j < 4; j++)
            tile[ty + 8 * j][tx] = s[(size_t)(ty + 8 * j) * 1024 + tx];
        __syncthreads();
        int t = ty * 32 + tx;
        int r2 = t & 15;
        int cl = t >> 4;
#pragma unroll
        for (int p = 0; p < 2; p++) {
            int c = cl + p * 16;
            float a = tile[r2 * 2][c], b = tile[r2 * 2 + 1][c];
            __half2 vh;
            vh.x = __float2half_rn(a);
            vh.y = __float2half_rn(b);
            size_t o = ((size_t)e * 1024 + c0 + c) * 1024 + r0 + r2 * 2;
            *(__half2*)(dst + o) = vh;
        }
    } else {
        int b = blockIdx.y * 32 + blockIdx.x;
        int t = ty * 32 + tx;
        size_t base = ((size_t)b * 256 + t) * 16;
#pragma unroll
        for (int v = 0; v < 4; v++) {
            size_t i = base + v * 4;
            float4 f4 = *(const float4*)(x + i);
            float f[4] = {f4.x, f4.y, f4.z, f4.w};
#pragma unroll
            for (int j = 0; j < 4; j += 2) {
                __half h0 = __float2half_rn(f[j]);
                __half h1 = __float2half_rn(f[j + 1]);
                __half l0 = __float2half_rn(f[j] - __half2float(h0));
                __half l1 = __float2half_rn(f[j + 1] - __half2float(h1));
                __half2 vh; vh.x = h0; vh.y = h1;
                __half2 vl; vl.x = l0; vl.y = l1;
                *(__half2*)(g_xh + i + j) = vh;
                *(__half2*)(g_xl + i + j) = vl;
            }
        }
    }
}

// ---------------- kernel 1: router (+ fused output zeroing) ---------------
__global__ void router_kernel(const float* __restrict__ x,
                              const float* __restrict__ rw,
                              float* __restrict__ out) {
    {
        size_t zb = ((size_t)(blockIdx.x * blockDim.x + threadIdx.x)) * 32;
        const float4 z4 = {0.0f, 0.0f, 0.0f, 0.0f};
#pragma unroll
        for (int j = 0; j < 8; j++) *(float4*)(out + zb + j * 4) = z4;
    }

    int warp = (blockIdx.x * blockDim.x + threadIdx.x) >> 5;
    int lane = threadIdx.x & 31;
    if (warp >= TT) return;
    const float* xr = x + (size_t)warp * DD;

    float acc[EE];
#pragma unroll
    for (int e = 0; e < EE; e++) acc[e] = 0.0f;
    for (int d = lane; d < DD; d += 32) {
        float xv = __ldg(xr + d);
        const float4* rwp = (const float4*)(rw + (size_t)d * EE);
#pragma unroll
        for (int q = 0; q < 4; q++) {
            float4 v = __ldg(rwp + q);
            acc[4 * q + 0] += xv * v.x;
            acc[4 * q + 1] += xv * v.y;
            acc[4 * q + 2] += xv * v.z;
            acc[4 * q + 3] += xv * v.w;
        }
    }
#pragma unroll
    for (int e = 0; e < EE; e++) {
#pragma unroll
        for (int off = 16; off; off >>= 1)
            acc[e] += __shfl_xor_sync(0xffffffffu, acc[e], off);
    }
    if (lane == 0) {
        int i1 = 0; float v1 = acc[0];
#pragma unroll
        for (int e = 1; e < EE; e++) if (acc[e] > v1) { v1 = acc[e]; i1 = e; }
        int i2 = -1; float v2 = -1e30f;
#pragma unroll
        for (int e = 0; e < EE; e++) {
            if (e == i1) continue;
            if (acc[e] > v2) { v2 = acc[e]; i2 = e; }
        }
        float mx = v1;
        float s = 0.0f;
#pragma unroll
        for (int e = 0; e < EE; e++) s += expf(acc[e] - mx);
        float w1 = expf(v1 - mx) / s;
        float w2 = expf(v2 - mx) / s;
        g_topk_idx[warp * 2 + 0] = i1;
        g_topk_idx[warp * 2 + 1] = i2;
        g_topk_w[warp * 2 + 0] = w1;
        g_topk_w[warp * 2 + 1] = w2;
    }
}

// ---------------- kernel 2: ordered rank scan + compaction ----------------
__global__ void scan_kernel() {
    __shared__ int cnt[512][EE];
    __shared__ int ecount[EE];
    int tid = threadIdx.x;
    int k = tid >> 8;
    int c = tid & 255;
    int t0 = c * 16;

#pragma unroll
    for (int e = 0; e < EE; e++) cnt[tid][e] = 0;
    if (tid < EE) ecount[tid] = 0;
    __syncthreads();

    for (int i = 0; i < 16; i++) {
        int e = g_topk_idx[(t0 + i) * 2 + k];
        cnt[tid][e]++;
    }
    __syncthreads();

    if (tid < 32) {
        int kk = tid >> 4, ee = tid & 15;
        int run = 0;
        for (int cc = 0; cc < 256; cc++) {
            int idx = kk * 256 + cc;
            int v = cnt[idx][ee];
            cnt[idx][ee] = run;
            run += v;
        }
    }
    __syncthreads();

    for (int i = 0; i < 16; i++) {
        int t = t0 + i;
        int e = g_topk_idx[t * 2 + k];
        float w = g_topk_w[t * 2 + k];
        int rank = cnt[tid][e]++;
        if (rank < CAP) {
            int slot = atomicAdd(&ecount[e], 1);
            g_disp_tok[e * CBUF + slot] = t;
            g_disp_w[e * CBUF + slot] = w;
        }
    }
    __syncthreads();
    if (tid < EE) g_count[tid] = ecount[tid];
}

// ---------------- kernel 3: gemm1 (fp16 A-split x2 MMA, dbl-buf) ----------
__global__ __launch_bounds__(256, 2)
void gemm1_kernel() {
    int e    = blockIdx.z;
    int mcnt = g_count[e];
    mcnt = (mcnt < 0) ? 0 : ((mcnt > CBUF) ? CBUF : mcnt);
    int m0   = blockIdx.y * BM;
    if (m0 >= mcnt) return;
    int h0 = blockIdx.x * 64;

    extern __shared__ __align__(16) unsigned char dsm[];   // 2 * G1_STG
    __shared__ int s_tok[BM];

    int tid  = threadIdx.x;
    int lane = tid & 31;
    int w    = tid >> 5;
    int mat  = w >> 2;        // 0 = gate, 1 = up
    int wm   = (w >> 1) & 1;  // m half (64 rows)
    int wn   = w & 1;         // n half (32 cols)
    uint32_t sbase = smem_u32(dsm);

    if (tid < BM) {
        int gr = m0 + tid;
        int tk = (gr < mcnt) ? g_disp_tok[e * CBUF + gr] : -1;
        if (tk < 0 || tk >= TT) tk = (gr < mcnt) ? 0 : -1;
        s_tok[tid] = tk;
    }
    __syncthreads();

    float acc[4][4][4];
#pragma unroll
    for (int im = 0; im < 4; im++)
#pragma unroll
        for (int in = 0; in < 4; in++)
#pragma unroll
            for (int r = 0; r < 4; r++) acc[im][in][r] = 0.0f;

    int g = lane >> 2, q = lane & 3;
    int ar  = wm * 64 + (lane & 15);
    int akb = (lane >> 4) << 4;
    int br  = wn * 32 + (lane & 7);
    int bkb = ((lane >> 3) & 1) << 4;

    // loader: A 1024 slots (2 splits x 128 rows x 4 16B), B 512 (2 tiles x 64 x 4)
    auto load_chunk = [&](int stg, int k0) {
        uint32_t sb = sbase + stg * G1_STG;
#pragma unroll
        for (int j = 0; j < 4; j++) {
            int s = tid + j * 256;
            int split = s >> 9;
            int r = (s >> 2) & 127;
            int c = s & 3;
            int tok = s_tok[r];
            const __half* src = split ? g_xl : g_xh;
            cp16(sb + (split ? G1_AL : G1_AH) + r * ROWB + c * 16,
                 src + (size_t)(tok < 0 ? 0 : tok) * DD + k0 + c * 8, tok >= 0);
        }
#pragma unroll
        for (int j = 0; j < 2; j++) {
            int s = tid + j * 256;
            int tile = s >> 8;
            int r = (s >> 2) & 63;
            int c = s & 3;
            const __half* src = tile ? g_uwT : g_gwT;
            cp16(sb + G1_B + tile * 5120 + r * ROWB + c * 16,
                 src + ((size_t)e * HH + h0 + r) * DD + k0 + c * 8, true);
        }
        CP_COMMIT();
    };

    load_chunk(0, 0);

    for (int ch = 0; ch < NCH; ch++) {
        int stg = ch & 1;
        CP_WAIT0();
        __syncthreads();
        if (ch + 1 < NCH) load_chunk(stg ^ 1, (ch + 1) * BK);

        uint32_t sb  = sbase + stg * G1_STG;
        uint32_t aHb = sb + G1_AH;
        uint32_t aLb = sb + G1_AL;
        uint32_t bb  = sb + G1_B + mat * 5120;

#pragma unroll
        for (int ks = 0; ks < 2; ks++) {
            uint32_t Bf[4][2];
#pragma unroll
            for (int in = 0; in < 4; in++) {
                uint32_t off = (uint32_t)(br + in * 8) * ROWB + ks * 32 + bkb;
                ldmx2(Bf[in], bb + off);
            }
#pragma unroll
            for (int imp = 0; imp < 2; imp++) {
                uint32_t Ah[2][4], Al[2][4];
#pragma unroll
                for (int i2 = 0; i2 < 2; i2++) {
                    uint32_t off = (uint32_t)(ar + (imp * 2 + i2) * 16) * ROWB + ks * 32 + akb;
                    ldmx4(Ah[i2], aHb + off);
                    ldmx4(Al[i2], aLb + off);
                }
                // pass-major: acc reuse distance = 8 mma
#pragma unroll
                for (int i2 = 0; i2 < 2; i2++)
#pragma unroll
                    for (int in = 0; in < 4; in++)
                        mma_f16(acc[imp * 2 + i2][in], Ah[i2], Bf[in]);
#pragma unroll
                for (int i2 = 0; i2 < 2; i2++)
#pragma unroll
                    for (int in = 0; in < 4; in++)
                        mma_f16(acc[imp * 2 + i2][in], Al[i2], Bf[in]);
            }
        }
    }
    __syncthreads();

    // ---- epilogue: up warps stage to smem; gate warps fuse silu(g)*u ----
    float* ex = (float*)dsm;   // 128 x 64 fp32 = 32 KB
    if (mat == 1) {
#pragma unroll
        for (int im = 0; im < 4; im++)
#pragma unroll
            for (int in = 0; in < 4; in++) {
                int rb = wm * 64 + im * 16 + g;
                int nb = wn * 32 + in * 8 + q * 2;
                ex[rb * 64 + nb]           = acc[im][in][0];
                ex[rb * 64 + nb + 1]       = acc[im][in][1];
                ex[(rb + 8) * 64 + nb]     = acc[im][in][2];
                ex[(rb + 8) * 64 + nb + 1] = acc[im][in][3];
            }
    }
    __syncthreads();
    if (mat == 0) {
#pragma unroll
        for (int im = 0; im < 4; im++)
#pragma unroll
            for (int in = 0; in < 4; in++) {
                int rb = wm * 64 + im * 16 + g;
                int nb = wn * 32 + in * 8 + q * 2;
#pragma unroll
                for (int h = 0; h < 2; h++) {
                    int r = rb + h * 8;
                    int gr = m0 + r;
                    if (gr < mcnt) {
                        float g0 = acc[im][in][h * 2], g1 = acc[im][in][h * 2 + 1];
                        float u0 = ex[r * 64 + nb], u1 = ex[r * 64 + nb + 1];
                        float f0 = (g0 / (1.0f + expf(-g0))) * u0;
                        float f1 = (g1 / (1.0f + expf(-g1))) * u1;
                        __half2 vh;
                        vh.x = __float2half_rn(f0);
                        vh.y = __float2half_rn(f1);
                        size_t o = ((size_t)e * CBUF + gr) * HH + h0 + nb;
                        *(__half2*)(g_hid + o) = vh;
                    }
                }
            }
    }
}

// ---------------- kernel 4: gemm2 (single-fp16 A, dbl-buf) ----------------
__global__ __launch_bounds__(256, 2)
void gemm2_kernel(float* __restrict__ out) {
    int e    = blockIdx.z;
    int mcnt = g_count[e];
    mcnt = (mcnt < 0) ? 0 : ((mcnt > CBUF) ? CBUF : mcnt);
    int m0   = blockIdx.y * BM;
    if (m0 >= mcnt) return;
    int d0 = blockIdx.x * 64;

    extern __shared__ __align__(16) unsigned char dsm[];   // 2 * G2_STG
    __shared__ int   s_tok[BM];
    __shared__ float s_w[BM];

    int tid  = threadIdx.x;
    int lane = tid & 31;
    int w    = tid >> 5;
    int wm   = w >> 1;   // 0..3
    int wn   = w & 1;    // 0..1
    uint32_t sbase = smem_u32(dsm);

    if (tid < BM) {
        int gr = m0 + tid;
        bool v = gr < mcnt;
        int tk = v ? g_disp_tok[e * CBUF + gr] : 0;
        if (tk < 0 || tk >= TT) tk = 0;
        s_tok[tid] = tk;
        s_w[tid]   = v ? g_disp_w[e * CBUF + gr] : 0.0f;
    }
    __syncthreads();

    float acc[2][4][4];
#pragma unroll
    for (int im = 0; im < 2; im++)
#pragma unroll
        for (int in = 0; in < 4; in++)
#pragma unroll
            for (int r = 0; r < 4; r++) acc[im][in][r] = 0.0f;

    int g = lane >> 2, q = lane & 3;
    int ar  = wm * 32 + (lane & 15);
    int akb = (lane >> 4) << 4;
    int br  = wn * 32 + (lane & 7);
    int bkb = ((lane >> 3) & 1) << 4;

    // loader: A 512 slots (128 rows x 4 16B), B 256 (64 rows x 4)
    auto load_chunk = [&](int stg, int k0) {
        uint32_t sb = sbase + stg * G2_STG;
#pragma unroll
        for (int j = 0; j < 2; j++) {
            int s = tid + j * 256;
            int r = s >> 2;
            int c = s & 3;
            bool v = (m0 + r) < mcnt;
            cp16(sb + G2_A + r * ROWB + c * 16,
                 g_hid + ((size_t)e * CBUF + (v ? m0 + r : 0)) * HH + k0 + c * 8, v);
        }
        {
            int r = tid >> 2;
            int c = tid & 3;
            cp16(sb + G2_B + r * ROWB + c * 16,
                 g_dwT + ((size_t)e * DD + d0 + r) * HH + k0 + c * 8, true);
        }
        CP_COMMIT();
    };

    load_chunk(0, 0);

    for (int ch = 0; ch < NCH; ch++) {
        int stg = ch & 1;
        CP_WAIT0();
        __syncthreads();
        if (ch + 1 < NCH) load_chunk(stg ^ 1, (ch + 1) * BK);

        uint32_t sb = sbase + stg * G2_STG;
        uint32_t ab = sb + G2_A;
        uint32_t bb = sb + G2_B;

#pragma unroll
        for (int ks = 0; ks < 2; ks++) {
            uint32_t Bf[4][2];
#pragma unroll
            for (int in = 0; in < 4; in++) {
                uint32_t off = (uint32_t)(br + in * 8) * ROWB + ks * 32 + bkb;
                ldmx2(Bf[in], bb + off);
            }
            uint32_t Af[2][4];
#pragma unroll
            for (int i2 = 0; i2 < 2; i2++) {
                uint32_t off = (uint32_t)(ar + i2 * 16) * ROWB + ks * 32 + akb;
                ldmx4(Af[i2], ab + off);
            }
#pragma unroll
            for (int i2 = 0; i2 < 2; i2++)
#pragma unroll
                for (int in = 0; in < 4; in++)
                    mma_f16(acc[i2][in], Af[i2], Bf[in]);
        }
    }

    // epilogue: weighted scatter-add into output
#pragma unroll
    for (int im = 0; im < 2; im++)
#pragma unroll
        for (int in = 0; in < 4; in++) {
            int rb = wm * 32 + im * 16 + g;
            int nb = wn * 32 + in * 8 + q * 2;
#pragma unroll
            for (int h = 0; h < 2; h++) {
                int r = rb + h * 8;
                int gr = m0 + r;
                if (gr < mcnt) {
                    float wt = s_w[r];
                    float* op = out + (size_t)s_tok[r] * DD + d0 + nb;
                    atomicAdd(op + 0, acc[im][in][h * 2] * wt);
                    atomicAdd(op + 1, acc[im][in][h * 2 + 1] * wt);
                }
            }
        }
}

// ---------------- launcher ----------------
extern "C" void kernel_launch(void* const* d_in, const int* in_sizes, int n_in,
                              void* d_out, int out_size) {
    const float* x  = (const float*)d_in[0];
    const float* rw = (const float*)d_in[1];
    const float* gw = (const float*)d_in[2];
    const float* uw = (const float*)d_in[3];
    const float* dw = (const float*)d_in[4];
    float* out = (float*)d_out;

    cudaFuncSetAttribute(gemm1_kernel, cudaFuncAttributeMaxDynamicSharedMemorySize, 2 * G1_STG);
    cudaFuncSetAttribute(gemm2_kernel, cudaFuncAttributeMaxDynamicSharedMemorySize, 2 * G2_STG);

    prep_kernel<<<dim3(32, 32, 49), dim3(32, 8)>>>(x, gw, uw, dw);            // idx 0
    router_kernel<<<TT / 8, 256>>>(x, rw, out);                               // idx 1
    scan_kernel<<<1, 512>>>();                                                // idx 2
    gemm1_kernel<<<dim3(HH / 64, CBUF / BM, EE), 256, 2 * G1_STG>>>();        // idx 3
    gemm2_kernel<<<dim3(DD / 64, CBUF / BM, EE), 256, 2 * G2_STG>>>(out);     // idx 4
}

// round 16
// speedup vs baseline: 1.5008x; 1.5008x over previous
#include <cuda_runtime.h>
#include <cuda_bf16.h>
#include <cuda_fp16.h>
#include <math.h>
#include <stdint.h>

// Problem constants
#define TT   4096      // tokens = B*S
#define DD   1024      // model dim
#define HH   1024      // hidden dim
#define EE   16        // experts
#define KK   2         // top-k
#define CAP  640       // capacity
#define CBUF 1280      // K*capacity

// GEMM tiling
#define BM    128      // token rows per block
#define BK    32       // K elements per smem chunk (fp16)
#define NCH   32       // 1024 / 32 chunks
#define ROWB  80       // padded smem row stride bytes (32*2 + 16)
#define NSTG  3        // pipeline stages

// gemm1 stage (30720 B): Ah@0 (128x80), Al@10240, B@20480 (2 tiles x 5120: gate, up)
#define G1_STG   30720
#define G1_AH    0
#define G1_AL    10240
#define G1_B     20480
// gemm2 stage (15360 B): A@0 (128x80), B@10240 (64x80)
#define G2_STG   15360
#define G2_A     0
#define G2_B     10240

// ---------------- PTX helpers ----------------
__device__ __forceinline__ uint32_t smem_u32(const void* p) {
    uint32_t a;
    asm("{ .reg .u64 t; cvta.to.shared.u64 t, %1; cvt.u32.u64 %0, t; }" : "=r"(a) : "l"(p));
    return a;
}
__device__ __forceinline__ void ldmx4(uint32_t* r, uint32_t a) {
    asm volatile("ldmatrix.sync.aligned.m8n8.x4.shared.b16 {%0,%1,%2,%3}, [%4];"
                 : "=r"(r[0]), "=r"(r[1]), "=r"(r[2]), "=r"(r[3]) : "r"(a));
}
__device__ __forceinline__ void ldmx2(uint32_t* r, uint32_t a) {
    asm volatile("ldmatrix.sync.aligned.m8n8.x2.shared.b16 {%0,%1}, [%2];"
                 : "=r"(r[0]), "=r"(r[1]) : "r"(a));
}
__device__ __forceinline__ void mma_f16(float* c, const uint32_t* a, const uint32_t* b) {
    asm volatile("mma.sync.aligned.m16n8k16.row.col.f32.f16.f16.f32 "
                 "{%0,%1,%2,%3}, {%4,%5,%6,%7}, {%8,%9}, {%0,%1,%2,%3};"
                 : "+f"(c[0]), "+f"(c[1]), "+f"(c[2]), "+f"(c[3])
                 : "r"(a[0]), "r"(a[1]), "r"(a[2]), "r"(a[3]), "r"(b[0]), "r"(b[1]));
}
__device__ __forceinline__ void cp16(uint32_t dst, const void* src, bool pred) {
    int sz = pred ? 16 : 0;
    asm volatile("cp.async.cg.shared.global [%0], [%1], 16, %2;"
                 :: "r"(dst), "l"(src), "r"(sz) : "memory");
}
#define CP_COMMIT() asm volatile("cp.async.commit_group;" ::: "memory")
#define CP_WAIT1()  asm volatile("cp.async.wait_group 1;" ::: "memory")
#define CP_WAIT0()  asm volatile("cp.async.wait_group 0;" ::: "memory")

// ---------------- device scratch ----------------
__device__ int   g_topk_idx[TT * KK];
__device__ float g_topk_w[TT * KK];
__device__ int   g_disp_tok[EE * CBUF];
__device__ float g_disp_w[EE * CBUF];
__device__ int   g_count[EE];

__device__ __align__(16) __half g_xh[(size_t)TT * DD];          // x hi (fp16)
__device__ __align__(16) __half g_xl[(size_t)TT * DD];          // x lo (fp16 residual)
__device__ __align__(16) __half g_gwT[(size_t)EE * HH * DD];    // [E][H][D] fp16
__device__ __align__(16) __half g_uwT[(size_t)EE * HH * DD];
__device__ __align__(16) __half g_dwT[(size_t)EE * DD * HH];    // [E][D][H] fp16
__device__ __align__(16) __half g_hid[(size_t)EE * CBUF * HH];  // hidden (single fp16)

// ---------------- kernel 0: fused prep ----------------
// z in [0,48): transpose+convert weight tensor to fp16 (z>>4: gw/uw/dw, z&15 = e)
// z == 48:     split x into fp16 hi/lo
__global__ void prep_kernel(const float* __restrict__ x,
                            const float* __restrict__ gw,
                            const float* __restrict__ uw,
                            const float* __restrict__ dw) {
    int z = blockIdx.z;
    int tx = threadIdx.x, ty = threadIdx.y;
    if (z < 48) {
        int which = z >> 4;
        int e = z & 15;
        const float* srcw = (which == 0) ? gw : (which == 1) ? uw : dw;
        __half* dst = (which == 0) ? g_gwT : (which == 1) ? g_uwT : g_dwT;

        __shared__ float tile[32][33];
        int r0 = blockIdx.y * 32;
        int c0 = blockIdx.x * 32;
        const float* s = srcw + ((size_t)e * 1024 + r0) * 1024 + c0;
#pragma unroll
        for (int j = 0; j < 4; j++)
            tile[ty + 8 * j][tx] = s[(size_t)(ty + 8 * j) * 1024 + tx];
        __syncthreads();
        int t = ty * 32 + tx;
        int r2 = t & 15;
        int cl = t >> 4;
#pragma unroll
        for (int p = 0; p < 2; p++) {
            int c = cl + p * 16;
            float a = tile[r2 * 2][c], b = tile[r2 * 2 + 1][c];
            __half2 vh;
            vh.x = __float2half_rn(a);
            vh.y = __float2half_rn(b);
            size_t o = ((size_t)e * 1024 + c0 + c) * 1024 + r0 + r2 * 2;
            *(__half2*)(dst + o) = vh;
        }
    } else {
        int b = blockIdx.y * 32 + blockIdx.x;
        int t = ty * 32 + tx;
        size_t base = ((size_t)b * 256 + t) * 16;
#pragma unroll
        for (int v = 0; v < 4; v++) {
            size_t i = base + v * 4;
            float4 f4 = *(const float4*)(x + i);
            float f[4] = {f4.x, f4.y, f4.z, f4.w};
#pragma unroll
            for (int j = 0; j < 4; j += 2) {
                __half h0 = __float2half_rn(f[j]);
                __half h1 = __float2half_rn(f[j + 1]);
                __half l0 = __float2half_rn(f[j] - __half2float(h0));
                __half l1 = __float2half_rn(f[j + 1] - __half2float(h1));
                __half2 vh; vh.x = h0; vh.y = h1;
                __half2 vl; vl.x = l0; vl.y = l1;
                *(__half2*)(g_xh + i + j) = vh;
                *(__half2*)(g_xl + i + j) = vl;
            }
        }
    }
}

// ---------------- kernel 1: router (+ fused output zeroing) ---------------
__global__ void router_kernel(const float* __restrict__ x,
                              const float* __restrict__ rw,
                              float* __restrict__ out) {
    {
        size_t zb = ((size_t)(blockIdx.x * blockDim.x + threadIdx.x)) * 32;
        const float4 z4 = {0.0f, 0.0f, 0.0f, 0.0f};
#pragma unroll
        for (int j = 0; j < 8; j++) *(float4*)(out + zb + j * 4) = z4;
    }

    int warp = (blockIdx.x * blockDim.x + threadIdx.x) >> 5;
    int lane = threadIdx.x & 31;
    if (warp >= TT) return;
    const float* xr = x + (size_t)warp * DD;

    float acc[EE];
#pragma unroll
    for (int e = 0; e < EE; e++) acc[e] = 0.0f;
    for (int d = lane; d < DD; d += 32) {
        float xv = __ldg(xr + d);
        const float4* rwp = (const float4*)(rw + (size_t)d * EE);
#pragma unroll
        for (int q = 0; q < 4; q++) {
            float4 v = __ldg(rwp + q);
            acc[4 * q + 0] += xv * v.x;
            acc[4 * q + 1] += xv * v.y;
            acc[4 * q + 2] += xv * v.z;
            acc[4 * q + 3] += xv * v.w;
        }
    }
#pragma unroll
    for (int e = 0; e < EE; e++) {
#pragma unroll
        for (int off = 16; off; off >>= 1)
            acc[e] += __shfl_xor_sync(0xffffffffu, acc[e], off);
    }
    if (lane == 0) {
        int i1 = 0; float v1 = acc[0];
#pragma unroll
        for (int e = 1; e < EE; e++) if (acc[e] > v1) { v1 = acc[e]; i1 = e; }
        int i2 = -1; float v2 = -1e30f;
#pragma unroll
        for (int e = 0; e < EE; e++) {
            if (e == i1) continue;
            if (acc[e] > v2) { v2 = acc[e]; i2 = e; }
        }
        float mx = v1;
        float s = 0.0f;
#pragma unroll
        for (int e = 0; e < EE; e++) s += expf(acc[e] - mx);
        float w1 = expf(v1 - mx) / s;
        float w2 = expf(v2 - mx) / s;
        g_topk_idx[warp * 2 + 0] = i1;
        g_topk_idx[warp * 2 + 1] = i2;
        g_topk_w[warp * 2 + 0] = w1;
        g_topk_w[warp * 2 + 1] = w2;
    }
}

// ---------------- kernel 2: ordered rank scan + compaction ----------------
__global__ void scan_kernel() {
    __shared__ int cnt[512][EE];
    __shared__ int ecount[EE];
    int tid = threadIdx.x;
    int k = tid >> 8;
    int c = tid & 255;
    int t0 = c * 16;

#pragma unroll
    for (int e = 0; e < EE; e++) cnt[tid][e] = 0;
    if (tid < EE) ecount[tid] = 0;
    __syncthreads();

    for (int i = 0; i < 16; i++) {
        int e = g_topk_idx[(t0 + i) * 2 + k];
        cnt[tid][e]++;
    }
    __syncthreads();

    if (tid < 32) {
        int kk = tid >> 4, ee = tid & 15;
        int run = 0;
        for (int cc = 0; cc < 256; cc++) {
            int idx = kk * 256 + cc;
            int v = cnt[idx][ee];
            cnt[idx][ee] = run;
            run += v;
        }
    }
    __syncthreads();

    for (int i = 0; i < 16; i++) {
        int t = t0 + i;
        int e = g_topk_idx[t * 2 + k];
        float w = g_topk_w[t * 2 + k];
        int rank = cnt[tid][e]++;
        if (rank < CAP) {
            int slot = atomicAdd(&ecount[e], 1);
            g_disp_tok[e * CBUF + slot] = t;
            g_disp_w[e * CBUF + slot] = w;
        }
    }
    __syncthreads();
    if (tid < EE) g_count[tid] = ecount[tid];
}

// ---------------- kernel 3: gemm1 (fp16 A-split, 3-stage cp.async) --------
__global__ __launch_bounds__(256, 2)
void gemm1_kernel() {
    int e    = blockIdx.z;
    int mcnt = g_count[e];
    mcnt = (mcnt < 0) ? 0 : ((mcnt > CBUF) ? CBUF : mcnt);
    int m0   = blockIdx.y * BM;
    if (m0 >= mcnt) return;
    int h0 = blockIdx.x * 64;

    extern __shared__ __align__(16) unsigned char dsm[];   // NSTG * G1_STG
    __shared__ int s_tok[BM];

    int tid  = threadIdx.x;
    int lane = tid & 31;
    int w    = tid >> 5;
    int mat  = w >> 2;        // 0 = gate, 1 = up
    int wm   = (w >> 1) & 1;  // m half (64 rows)
    int wn   = w & 1;         // n half (32 cols)
    uint32_t sbase = smem_u32(dsm);

    if (tid < BM) {
        int gr = m0 + tid;
        int tk = (gr < mcnt) ? g_disp_tok[e * CBUF + gr] : -1;
        if (tk < 0 || tk >= TT) tk = (gr < mcnt) ? 0 : -1;
        s_tok[tid] = tk;
    }
    __syncthreads();

    float acc[4][4][4];
#pragma unroll
    for (int im = 0; im < 4; im++)
#pragma unroll
        for (int in = 0; in < 4; in++)
#pragma unroll
            for (int r = 0; r < 4; r++) acc[im][in][r] = 0.0f;

    int g = lane >> 2, q = lane & 3;
    int ar  = wm * 64 + (lane & 15);
    int akb = (lane >> 4) << 4;
    int br  = wn * 32 + (lane & 7);
    int bkb = ((lane >> 3) & 1) << 4;

    // loader: A 1024 slots (2 splits x 128 rows x 4 16B), B 512 (2 tiles x 64 x 4)
    auto load_chunk = [&](int stg, int k0) {
        uint32_t sb = sbase + stg * G1_STG;
#pragma unroll
        for (int j = 0; j < 4; j++) {
            int s = tid + j * 256;
            int split = s >> 9;
            int r = (s >> 2) & 127;
            int c = s & 3;
            int tok = s_tok[r];
            const __half* src = split ? g_xl : g_xh;
            cp16(sb + (split ? G1_AL : G1_AH) + r * ROWB + c * 16,
                 src + (size_t)(tok < 0 ? 0 : tok) * DD + k0 + c * 8, tok >= 0);
        }
#pragma unroll
        for (int j = 0; j < 2; j++) {
            int s = tid + j * 256;
            int tile = s >> 8;
            int r = (s >> 2) & 63;
            int c = s & 3;
            const __half* src = tile ? g_uwT : g_gwT;
            cp16(sb + G1_B + tile * 5120 + r * ROWB + c * 16,
                 src + ((size_t)e * HH + h0 + r) * DD + k0 + c * 8, true);
        }
        CP_COMMIT();
    };

    load_chunk(0, 0);
    load_chunk(1, BK);

    for (int ch = 0; ch < NCH; ch++) {
        int stg = ch % NSTG;
        // at loop top: groups in flight = {ch, ch+1} (or just {ch} on last iter)
        if (ch + 1 < NCH) CP_WAIT1(); else CP_WAIT0();
        // one barrier: data of chunk ch visible AND stage (ch+2)%3 free
        // (all warps finished consuming chunk ch-1, which freed that stage)
        __syncthreads();
        if (ch + 2 < NCH) load_chunk((ch + 2) % NSTG, (ch + 2) * BK);

        uint32_t sb  = sbase + stg * G1_STG;
        uint32_t aHb = sb + G1_AH;
        uint32_t aLb = sb + G1_AL;
        uint32_t bb  = sb + G1_B + mat * 5120;

#pragma unroll
        for (int ks = 0; ks < 2; ks++) {
            uint32_t Bf[4][2];
#pragma unroll
            for (int in = 0; in < 4; in++) {
                uint32_t off = (uint32_t)(br + in * 8) * ROWB + ks * 32 + bkb;
                ldmx2(Bf[in], bb + off);
            }
#pragma unroll
            for (int imp = 0; imp < 2; imp++) {
                uint32_t Ah[2][4], Al[2][4];
#pragma unroll
                for (int i2 = 0; i2 < 2; i2++) {
                    uint32_t off = (uint32_t)(ar + (imp * 2 + i2) * 16) * ROWB + ks * 32 + akb;
                    ldmx4(Ah[i2], aHb + off);
                    ldmx4(Al[i2], aLb + off);
                }
                // pass-major: acc reuse distance = 8 mma
#pragma unroll
                for (int i2 = 0; i2 < 2; i2++)
#pragma unroll
                    for (int in = 0; in < 4; in++)
                        mma_f16(acc[imp * 2 + i2][in], Ah[i2], Bf[in]);
#pragma unroll
                for (int i2 = 0; i2 < 2; i2++)
#pragma unroll
                    for (int in = 0; in < 4; in++)
                        mma_f16(acc[imp * 2 + i2][in], Al[i2], Bf[in]);
            }
        }
    }
    __syncthreads();

    // ---- epilogue: up warps stage to smem; gate warps fuse silu(g)*u ----
    float* ex = (float*)dsm;   // 128 x 64 fp32 = 32 KB
    if (mat == 1) {
#pragma unroll
        for (int im = 0; im < 4; im++)
#pragma unroll
            for (int in = 0; in < 4; in++) {
                int rb = wm * 64 + im * 16 + g;
                int nb = wn * 32 + in * 8 + q * 2;
                ex[rb * 64 + nb]           = acc[im][in][0];
                ex[rb * 64 + nb + 1]       = acc[im][in][1];
                ex[(rb + 8) * 64 + nb]     = acc[im][in][2];
                ex[(rb + 8) * 64 + nb + 1] = acc[im][in][3];
            }
    }
    __syncthreads();
    if (mat == 0) {
#pragma unroll
        for (int im = 0; im < 4; im++)
#pragma unroll
            for (int in = 0; in < 4; in++) {
                int rb = wm * 64 + im * 16 + g;
                int nb = wn * 32 + in * 8 + q * 2;
#pragma unroll
                for (int h = 0; h < 2; h++) {
                    int r = rb + h * 8;
                    int gr = m0 + r;
                    if (gr < mcnt) {
                        float g0 = acc[im][in][h * 2], g1 = acc[im][in][h * 2 + 1];
                        float u0 = ex[r * 64 + nb], u1 = ex[r * 64 + nb + 1];
                        float f0 = (g0 / (1.0f + expf(-g0))) * u0;
                        float f1 = (g1 / (1.0f + expf(-g1))) * u1;
                        __half2 vh;
                        vh.x = __float2half_rn(f0);
                        vh.y = __float2half_rn(f1);
                        size_t o = ((size_t)e * CBUF + gr) * HH + h0 + nb;
                        *(__half2*)(g_hid + o) = vh;
                    }
                }
            }
    }
}

// ---------------- kernel 4: gemm2 (single-fp16 A, 3-stage cp.async) -------
__global__ __launch_bounds__(256, 2)
void gemm2_kernel(float* __restrict__ out) {
    int e    = blockIdx.z;
    int mcnt = g_count[e];
    mcnt = (mcnt < 0) ? 0 : ((mcnt > CBUF) ? CBUF : mcnt);
    int m0   = blockIdx.y * BM;
    if (m0 >= mcnt) return;
    int d0 = blockIdx.x * 64;

    extern __shared__ __align__(16) unsigned char dsm[];   // NSTG * G2_STG
    __shared__ int   s_tok[BM];
    __shared__ float s_w[BM];

    int tid  = threadIdx.x;
    int lane = tid & 31;
    int w    = tid >> 5;
    int wm   = w >> 1;   // 0..3
    int wn   = w & 1;    // 0..1
    uint32_t sbase = smem_u32(dsm);

    if (tid < BM) {
        int gr = m0 + tid;
        bool v = gr < mcnt;
        int tk = v ? g_disp_tok[e * CBUF + gr] : 0;
        if (tk < 0 || tk >= TT) tk = 0;
        s_tok[tid] = tk;
        s_w[tid]   = v ? g_disp_w[e * CBUF + gr] : 0.0f;
    }
    __syncthreads();

    float acc[2][4][4];
#pragma unroll
    for (int im = 0; im < 2; im++)
#pragma unroll
        for (int in = 0; in < 4; in++)
#pragma unroll
            for (int r = 0; r < 4; r++) acc[im][in][r] = 0.0f;

    int g = lane >> 2, q = lane & 3;
    int ar  = wm * 32 + (lane & 15);
    int akb = (lane >> 4) << 4;
    int br  = wn * 32 + (lane & 7);
    int bkb = ((lane >> 3) & 1) << 4;

    // loader: A 512 slots (128 rows x 4 16B), B 256 (64 rows x 4)
    auto load_chunk = [&](int stg, int k0) {
        uint32_t sb = sbase + stg * G2_STG;
#pragma unroll
        for (int j = 0; j < 2; j++) {
            int s = tid + j * 256;
            int r = s >> 2;
            int c = s & 3;
            bool v = (m0 + r) < mcnt;
            cp16(sb + G2_A + r * ROWB + c * 16,
                 g_hid + ((size_t)e * CBUF + (v ? m0 + r : 0)) * HH + k0 + c * 8, v);
        }
        {
            int r = tid >> 2;
            int c = tid & 3;
            cp16(sb + G2_B + r * ROWB + c * 16,
                 g_dwT + ((size_t)e * DD + d0 + r) * HH + k0 + c * 8, true);
        }
        CP_COMMIT();
    };

    load_chunk(0, 0);
    load_chunk(1, BK);

    for (int ch = 0; ch < NCH; ch++) {
        int stg = ch % NSTG;
        if (ch + 1 < NCH) CP_WAIT1(); else CP_WAIT0();
        __syncthreads();
        if (ch + 2 < NCH) load_chunk((ch + 2) % NSTG, (ch + 2) * BK);

        uint32_t sb = sbase + stg * G2_STG;
        uint32_t ab = sb + G2_A;
        uint32_t bb = sb + G2_B;

#pragma unroll
        for (int ks = 0; ks < 2; ks++) {
            uint32_t Bf[4][2];
#pragma unroll
            for (int in = 0; in < 4; in++) {
                uint32_t off = (uint32_t)(br + in * 8) * ROWB + ks * 32 + bkb;
                ldmx2(Bf[in], bb + off);
            }
            uint32_t Af[2][4];
#pragma unroll
            for (int i2 = 0; i2 < 2; i2++) {
                uint32_t off = (uint32_t)(ar + i2 * 16) * ROWB + ks * 32 + akb;
                ldmx4(Af[i2], ab + off);
            }
#pragma unroll
            for (int i2 = 0; i2 < 2; i2++)
#pragma unroll
                for (int in = 0; in < 4; in++)
                    mma_f16(acc[i2][in], Af[i2], Bf[in]);
        }
    }

    // epilogue: weighted scatter-add into output
#pragma unroll
    for (int im = 0; im < 2; im++)
#pragma unroll
        for (int in = 0; in < 4; in++) {
            int rb = wm * 32 + im * 16 + g;
            int nb = wn * 32 + in * 8 + q * 2;
#pragma unroll
            for (int h = 0; h < 2; h++) {
                int r = rb + h * 8;
                int gr = m0 + r;
                if (gr < mcnt) {
                    float wt = s_w[r];
                    float* op = out + (size_t)s_tok[r] * DD + d0 + nb;
                    atomicAdd(op + 0, acc[im][in][h * 2] * wt);
                    atomicAdd(op + 1, acc[im][in][h * 2 + 1] * wt);
                }
            }
        }
}

// ---------------- launcher ----------------
extern "C" void kernel_launch(void* const* d_in, const int* in_sizes, int n_in,
                              void* d_out, int out_size) {
    const float* x  = (const float*)d_in[0];
    const float* rw = (const float*)d_in[1];
    const float* gw = (const float*)d_in[2];
    const float* uw = (const float*)d_in[3];
    const float* dw = (const float*)d_in[4];
    float* out = (float*)d_out;

    cudaFuncSetAttribute(gemm1_kernel, cudaFuncAttributeMaxDynamicSharedMemorySize, NSTG * G1_STG);
    cudaFuncSetAttribute(gemm2_kernel, cudaFuncAttributeMaxDynamicSharedMemorySize, NSTG * G2_STG);

    prep_kernel<<<dim3(32, 32, 49), dim3(32, 8)>>>(x, gw, uw, dw);               // idx 0
    router_kernel<<<TT / 8, 256>>>(x, rw, out);                                  // idx 1
    scan_kernel<<<1, 512>>>();                                                   // idx 2
    gemm1_kernel<<<dim3(HH / 64, CBUF / BM, EE), 256, NSTG * G1_STG>>>();        // idx 3
    gemm2_kernel<<<dim3(DD / 64, CBUF / BM, EE), 256, NSTG * G2_STG>>>(out);     // idx 4
}

// round 17
// speedup vs baseline: 1.8819x; 1.2540x over previous
#include <cuda_runtime.h>
#include <cuda_bf16.h>
#include <cuda_fp16.h>
#include <math.h>
#include <stdint.h>

// Problem constants
#define TT   4096      // tokens = B*S
#define DD   1024      // model dim
#define HH   1024      // hidden dim
#define EE   16        // experts
#define KK   2         // top-k
#define CAP  640       // capacity
#define CBUF 1280      // K*capacity

// GEMM tiling
#define BM    128      // token rows per block
#define BK    32       // K elements per smem chunk (fp16)
#define NCH   32       // 1024 / 32 chunks
#define ROWB  80       // padded smem row stride bytes (32*2 + 16)
#define NSTG  3        // pipeline stages

// gemm1 stage (20480 B): A@0 (128x80), B@10240 (2 tiles x 5120: gate, up)
#define G1_STG   20480
#define G1_A     0
#define G1_B     10240
// gemm2 stage (15360 B): A@0 (128x80), B@10240 (64x80)
#define G2_STG   15360
#define G2_A     0
#define G2_B     10240

// ---------------- PTX helpers ----------------
__device__ __forceinline__ uint32_t smem_u32(const void* p) {
    uint32_t a;
    asm("{ .reg .u64 t; cvta.to.shared.u64 t, %1; cvt.u32.u64 %0, t; }" : "=r"(a) : "l"(p));
    return a;
}
__device__ __forceinline__ void ldmx4(uint32_t* r, uint32_t a) {
    asm volatile("ldmatrix.sync.aligned.m8n8.x4.shared.b16 {%0,%1,%2,%3}, [%4];"
                 : "=r"(r[0]), "=r"(r[1]), "=r"(r[2]), "=r"(r[3]) : "r"(a));
}
__device__ __forceinline__ void ldmx2(uint32_t* r, uint32_t a) {
    asm volatile("ldmatrix.sync.aligned.m8n8.x2.shared.b16 {%0,%1}, [%2];"
                 : "=r"(r[0]), "=r"(r[1]) : "r"(a));
}
__device__ __forceinline__ void mma_f16(float* c, const uint32_t* a, const uint32_t* b) {
    asm volatile("mma.sync.aligned.m16n8k16.row.col.f32.f16.f16.f32 "
                 "{%0,%1,%2,%3}, {%4,%5,%6,%7}, {%8,%9}, {%0,%1,%2,%3};"
                 : "+f"(c[0]), "+f"(c[1]), "+f"(c[2]), "+f"(c[3])
                 : "r"(a[0]), "r"(a[1]), "r"(a[2]), "r"(a[3]), "r"(b[0]), "r"(b[1]));
}
__device__ __forceinline__ void cp16(uint32_t dst, const void* src, bool pred) {
    int sz = pred ? 16 : 0;
    asm volatile("cp.async.cg.shared.global [%0], [%1], 16, %2;"
                 :: "r"(dst), "l"(src), "r"(sz) : "memory");
}
#define CP_COMMIT() asm volatile("cp.async.commit_group;" ::: "memory")
#define CP_WAIT1()  asm volatile("cp.async.wait_group 1;" ::: "memory")
#define CP_WAIT0()  asm volatile("cp.async.wait_group 0;" ::: "memory")

// ---------------- device scratch ----------------
__device__ int   g_topk_idx[TT * KK];
__device__ float g_topk_w[TT * KK];
__device__ int   g_disp_tok[EE * CBUF];
__device__ float g_disp_w[EE * CBUF];
__device__ int   g_count[EE];

__device__ __align__(16) __half g_x16[(size_t)TT * DD];         // x (single fp16)
__device__ __align__(16) __half g_gwT[(size_t)EE * HH * DD];    // [E][H][D] fp16
__device__ __align__(16) __half g_uwT[(size_t)EE * HH * DD];
__device__ __align__(16) __half g_dwT[(size_t)EE * DD * HH];    // [E][D][H] fp16
__device__ __align__(16) __half g_hid[(size_t)EE * CBUF * HH];  // hidden (single fp16)

// ---------------- kernel 0: fused prep ----------------
// z in [0,48): transpose+convert weight tensor to fp16 (z>>4: gw/uw/dw, z&15 = e)
// z == 48:     convert x to fp16
__global__ void prep_kernel(const float* __restrict__ x,
                            const float* __restrict__ gw,
                            const float* __restrict__ uw,
                            const float* __restrict__ dw) {
    int z = blockIdx.z;
    int tx = threadIdx.x, ty = threadIdx.y;
    if (z < 48) {
        int which = z >> 4;
        int e = z & 15;
        const float* srcw = (which == 0) ? gw : (which == 1) ? uw : dw;
        __half* dst = (which == 0) ? g_gwT : (which == 1) ? g_uwT : g_dwT;

        __shared__ float tile[32][33];
        int r0 = blockIdx.y * 32;
        int c0 = blockIdx.x * 32;
        const float* s = srcw + ((size_t)e * 1024 + r0) * 1024 + c0;
#pragma unroll
        for (int j = 0; j < 4; j++)
            tile[ty + 8 * j][tx] = s[(size_t)(ty + 8 * j) * 1024 + tx];
        __syncthreads();
        int t = ty * 32 + tx;
        int r2 = t & 15;
        int cl = t >> 4;
#pragma unroll
        for (int p = 0; p < 2; p++) {
            int c = cl + p * 16;
            float a = tile[r2 * 2][c], b = tile[r2 * 2 + 1][c];
            __half2 vh;
            vh.x = __float2half_rn(a);
            vh.y = __float2half_rn(b);
            size_t o = ((size_t)e * 1024 + c0 + c) * 1024 + r0 + r2 * 2;
            *(__half2*)(dst + o) = vh;
        }
    } else {
        int b = blockIdx.y * 32 + blockIdx.x;
        int t = ty * 32 + tx;
        size_t base = ((size_t)b * 256 + t) * 16;
#pragma unroll
        for (int v = 0; v < 4; v++) {
            size_t i = base + v * 4;
            float4 f4 = *(const float4*)(x + i);
            __half2 h0; h0.x = __float2half_rn(f4.x); h0.y = __float2half_rn(f4.y);
            __half2 h1; h1.x = __float2half_rn(f4.z); h1.y = __float2half_rn(f4.w);
            *(__half2*)(g_x16 + i)     = h0;
            *(__half2*)(g_x16 + i + 2) = h1;
        }
    }
}

// ---------------- kernel 1: router (+ fused output zeroing) ---------------
__global__ void router_kernel(const float* __restrict__ x,
                              const float* __restrict__ rw,
                              float* __restrict__ out) {
    {
        size_t zb = ((size_t)(blockIdx.x * blockDim.x + threadIdx.x)) * 32;
        const float4 z4 = {0.0f, 0.0f, 0.0f, 0.0f};
#pragma unroll
        for (int j = 0; j < 8; j++) *(float4*)(out + zb + j * 4) = z4;
    }

    int warp = (blockIdx.x * blockDim.x + threadIdx.x) >> 5;
    int lane = threadIdx.x & 31;
    if (warp >= TT) return;
    const float* xr = x + (size_t)warp * DD;

    float acc[EE];
#pragma unroll
    for (int e = 0; e < EE; e++) acc[e] = 0.0f;
    for (int d = lane; d < DD; d += 32) {
        float xv = __ldg(xr + d);
        const float4* rwp = (const float4*)(rw + (size_t)d * EE);
#pragma unroll
        for (int q = 0; q < 4; q++) {
            float4 v = __ldg(rwp + q);
            acc[4 * q + 0] += xv * v.x;
            acc[4 * q + 1] += xv * v.y;
            acc[4 * q + 2] += xv * v.z;
            acc[4 * q + 3] += xv * v.w;
        }
    }
#pragma unroll
    for (int e = 0; e < EE; e++) {
#pragma unroll
        for (int off = 16; off; off >>= 1)
            acc[e] += __shfl_xor_sync(0xffffffffu, acc[e], off);
    }
    if (lane == 0) {
        int i1 = 0; float v1 = acc[0];
#pragma unroll
        for (int e = 1; e < EE; e++) if (acc[e] > v1) { v1 = acc[e]; i1 = e; }
        int i2 = -1; float v2 = -1e30f;
#pragma unroll
        for (int e = 0; e < EE; e++) {
            if (e == i1) continue;
            if (acc[e] > v2) { v2 = acc[e]; i2 = e; }
        }
        float mx = v1;
        float s = 0.0f;
#pragma unroll
        for (int e = 0; e < EE; e++) s += expf(acc[e] - mx);
        float w1 = expf(v1 - mx) / s;
        float w2 = expf(v2 - mx) / s;
        g_topk_idx[warp * 2 + 0] = i1;
        g_topk_idx[warp * 2 + 1] = i2;
        g_topk_w[warp * 2 + 0] = w1;
        g_topk_w[warp * 2 + 1] = w2;
    }
}

// ---------------- kernel 2: ordered rank scan + compaction ----------------
__global__ void scan_kernel() {
    __shared__ int cnt[512][EE];
    __shared__ int ecount[EE];
    int tid = threadIdx.x;
    int k = tid >> 8;
    int c = tid & 255;
    int t0 = c * 16;

#pragma unroll
    for (int e = 0; e < EE; e++) cnt[tid][e] = 0;
    if (tid < EE) ecount[tid] = 0;
    __syncthreads();

    for (int i = 0; i < 16; i++) {
        int e = g_topk_idx[(t0 + i) * 2 + k];
        cnt[tid][e]++;
    }
    __syncthreads();

    if (tid < 32) {
        int kk = tid >> 4, ee = tid & 15;
        int run = 0;
        for (int cc = 0; cc < 256; cc++) {
            int idx = kk * 256 + cc;
            int v = cnt[idx][ee];
            cnt[idx][ee] = run;
            run += v;
        }
    }
    __syncthreads();

    for (int i = 0; i < 16; i++) {
        int t = t0 + i;
        int e = g_topk_idx[t * 2 + k];
        float w = g_topk_w[t * 2 + k];
        int rank = cnt[tid][e]++;
        if (rank < CAP) {
            int slot = atomicAdd(&ecount[e], 1);
            g_disp_tok[e * CBUF + slot] = t;
            g_disp_w[e * CBUF + slot] = w;
        }
    }
    __syncthreads();
    if (tid < EE) g_count[tid] = ecount[tid];
}

// ---------------- kernel 3: gemm1 (single-fp16, 3-stage cp.async) ---------
__global__ __launch_bounds__(256, 2)
void gemm1_kernel() {
    int e    = blockIdx.z;
    int mcnt = g_count[e];
    mcnt = (mcnt < 0) ? 0 : ((mcnt > CBUF) ? CBUF : mcnt);
    int m0   = blockIdx.y * BM;
    if (m0 >= mcnt) return;
    int h0 = blockIdx.x * 64;

    extern __shared__ __align__(16) unsigned char dsm[];   // NSTG * G1_STG
    __shared__ int s_tok[BM];

    int tid  = threadIdx.x;
    int lane = tid & 31;
    int w    = tid >> 5;
    int mat  = w >> 2;        // 0 = gate, 1 = up
    int wm   = (w >> 1) & 1;  // m half (64 rows)
    int wn   = w & 1;         // n half (32 cols)
    uint32_t sbase = smem_u32(dsm);

    if (tid < BM) {
        int gr = m0 + tid;
        int tk = (gr < mcnt) ? g_disp_tok[e * CBUF + gr] : -1;
        if (tk < 0 || tk >= TT) tk = (gr < mcnt) ? 0 : -1;
        s_tok[tid] = tk;
    }
    __syncthreads();

    float acc[4][4][4];
#pragma unroll
    for (int im = 0; im < 4; im++)
#pragma unroll
        for (int in = 0; in < 4; in++)
#pragma unroll
            for (int r = 0; r < 4; r++) acc[im][in][r] = 0.0f;

    int g = lane >> 2, q = lane & 3;
    int ar  = wm * 64 + (lane & 15);
    int akb = (lane >> 4) << 4;
    int br  = wn * 32 + (lane & 7);
    int bkb = ((lane >> 3) & 1) << 4;

    // loader: A 512 slots (128 rows x 4 16B), B 512 (2 tiles x 64 x 4)
    auto load_chunk = [&](int stg, int k0) {
        uint32_t sb = sbase + stg * G1_STG;
#pragma unroll
        for (int j = 0; j < 2; j++) {
            int s = tid + j * 256;
            int r = s >> 2;
            int c = s & 3;
            int tok = s_tok[r];
            cp16(sb + G1_A + r * ROWB + c * 16,
                 g_x16 + (size_t)(tok < 0 ? 0 : tok) * DD + k0 + c * 8, tok >= 0);
        }
#pragma unroll
        for (int j = 0; j < 2; j++) {
            int s = tid + j * 256;
            int tile = s >> 8;
            int r = (s >> 2) & 63;
            int c = s & 3;
            const __half* src = tile ? g_uwT : g_gwT;
            cp16(sb + G1_B + tile * 5120 + r * ROWB + c * 16,
                 src + ((size_t)e * HH + h0 + r) * DD + k0 + c * 8, true);
        }
        CP_COMMIT();
    };

    load_chunk(0, 0);
    load_chunk(1, BK);

    for (int ch = 0; ch < NCH; ch++) {
        int stg = ch % NSTG;
        if (ch + 1 < NCH) CP_WAIT1(); else CP_WAIT0();
        // one barrier: data of chunk ch visible AND stage (ch+2)%3 free
        __syncthreads();
        if (ch + 2 < NCH) load_chunk((ch + 2) % NSTG, (ch + 2) * BK);

        uint32_t sb = sbase + stg * G1_STG;
        uint32_t ab = sb + G1_A;
        uint32_t bb = sb + G1_B + mat * 5120;

#pragma unroll
        for (int ks = 0; ks < 2; ks++) {
            uint32_t Bf[4][2];
#pragma unroll
            for (int in = 0; in < 4; in++) {
                uint32_t off = (uint32_t)(br + in * 8) * ROWB + ks * 32 + bkb;
                ldmx2(Bf[in], bb + off);
            }
            uint32_t Af[4][4];
#pragma unroll
            for (int im = 0; im < 4; im++) {
                uint32_t off = (uint32_t)(ar + im * 16) * ROWB + ks * 32 + akb;
                ldmx4(Af[im], ab + off);
            }
            // each accumulator touched once per ks: reuse distance 16 MMAs
#pragma unroll
            for (int im = 0; im < 4; im++)
#pragma unroll
                for (int in = 0; in < 4; in++)
                    mma_f16(acc[im][in], Af[im], Bf[in]);
        }
    }
    __syncthreads();

    // ---- epilogue: up warps stage to smem; gate warps fuse silu(g)*u ----
    float* ex = (float*)dsm;   // 128 x 64 fp32 = 32 KB
    if (mat == 1) {
#pragma unroll
        for (int im = 0; im < 4; im++)
#pragma unroll
            for (int in = 0; in < 4; in++) {
                int rb = wm * 64 + im * 16 + g;
                int nb = wn * 32 + in * 8 + q * 2;
                ex[rb * 64 + nb]           = acc[im][in][0];
                ex[rb * 64 + nb + 1]       = acc[im][in][1];
                ex[(rb + 8) * 64 + nb]     = acc[im][in][2];
                ex[(rb + 8) * 64 + nb + 1] = acc[im][in][3];
            }
    }
    __syncthreads();
    if (mat == 0) {
#pragma unroll
        for (int im = 0; im < 4; im++)
#pragma unroll
            for (int in = 0; in < 4; in++) {
                int rb = wm * 64 + im * 16 + g;
                int nb = wn * 32 + in * 8 + q * 2;
#pragma unroll
                for (int h = 0; h < 2; h++) {
                    int r = rb + h * 8;
                    int gr = m0 + r;
                    if (gr < mcnt) {
                        float g0 = acc[im][in][h * 2], g1 = acc[im][in][h * 2 + 1];
                        float u0 = ex[r * 64 + nb], u1 = ex[r * 64 + nb + 1];
                        float f0 = (g0 / (1.0f + expf(-g0))) * u0;
                        float f1 = (g1 / (1.0f + expf(-g1))) * u1;
                        __half2 vh;
                        vh.x = __float2half_rn(f0);
                        vh.y = __float2half_rn(f1);
                        size_t o = ((size_t)e * CBUF + gr) * HH + h0 + nb;
                        *(__half2*)(g_hid + o) = vh;
                    }
                }
            }
    }
}

// ---------------- kernel 4: gemm2 (single-fp16 A, 3-stage cp.async) -------
__global__ __launch_bounds__(256, 2)
void gemm2_kernel(float* __restrict__ out) {
    int e    = blockIdx.z;
    int mcnt = g_count[e];
    mcnt = (mcnt < 0) ? 0 : ((mcnt > CBUF) ? CBUF : mcnt);
    int m0   = blockIdx.y * BM;
    if (m0 >= mcnt) return;
    int d0 = blockIdx.x * 64;

    extern __shared__ __align__(16) unsigned char dsm[];   // NSTG * G2_STG
    __shared__ int   s_tok[BM];
    __shared__ float s_w[BM];

    int tid  = threadIdx.x;
    int lane = tid & 31;
    int w    = tid >> 5;
    int wm   = w >> 1;   // 0..3
    int wn   = w & 1;    // 0..1
    uint32_t sbase = smem_u32(dsm);

    if (tid < BM) {
        int gr = m0 + tid;
        bool v = gr < mcnt;
        int tk = v ? g_disp_tok[e * CBUF + gr] : 0;
        if (tk < 0 || tk >= TT) tk = 0;
        s_tok[tid] = tk;
        s_w[tid]   = v ? g_disp_w[e * CBUF + gr] : 0.0f;
    }
    __syncthreads();

    float acc[2][4][4];
#pragma unroll
    for (int im = 0; im < 2; im++)
#pragma unroll
        for (int in = 0; in < 4; in++)
#pragma unroll
            for (int r = 0; r < 4; r++) acc[im][in][r] = 0.0f;

    int g = lane >> 2, q = lane & 3;
    int ar  = wm * 32 + (lane & 15);
    int akb = (lane >> 4) << 4;
    int br  = wn * 32 + (lane & 7);
    int bkb = ((lane >> 3) & 1) << 4;

    // loader: A 512 slots (128 rows x 4 16B), B 256 (64 rows x 4)
    auto load_chunk = [&](int stg, int k0) {
        uint32_t sb = sbase + stg * G2_STG;
#pragma unroll
        for (int j = 0; j < 2; j++) {
            int s = tid + j * 256;
            int r = s >> 2;
            int c = s & 3;
            bool v = (m0 + r) < mcnt;
            cp16(sb + G2_A + r * ROWB + c * 16,
                 g_hid + ((size_t)e * CBUF + (v ? m0 + r : 0)) * HH + k0 + c * 8, v);
        }
        {
            int r = tid >> 2;
            int c = tid & 3;
            cp16(sb + G2_B + r * ROWB + c * 16,
                 g_dwT + ((size_t)e * DD + d0 + r) * HH + k0 + c * 8, true);
        }
        CP_COMMIT();
    };

    load_chunk(0, 0);
    load_chunk(1, BK);

    for (int ch = 0; ch < NCH; ch++) {
        int stg = ch % NSTG;
        if (ch + 1 < NCH) CP_WAIT1(); else CP_WAIT0();
        __syncthreads();
        if (ch + 2 < NCH) load_chunk((ch + 2) % NSTG, (ch + 2) * BK);

        uint32_t sb = sbase + stg * G2_STG;
        uint32_t ab = sb + G2_A;
        uint32_t bb = sb + G2_B;

#pragma unroll
        for (int ks = 0; ks < 2; ks++) {
            uint32_t Bf[4][2];
#pragma unroll
            for (int in = 0; in < 4; in++) {
                uint32_t off = (uint32_t)(br + in * 8) * ROWB + ks * 32 + bkb;
                ldmx2(Bf[in], bb + off);
            }
            uint32_t Af[2][4];
#pragma unroll
            for (int i2 = 0; i2 < 2; i2++) {
                uint32_t off = (uint32_t)(ar + i2 * 16) * ROWB + ks * 32 + akb;
                ldmx4(Af[i2], ab + off);
            }
#pragma unroll
            for (int i2 = 0; i2 < 2; i2++)
#pragma unroll
                for (int in = 0; in < 4; in++)
                    mma_f16(acc[i2][in], Af[i2], Bf[in]);
        }
    }

    // epilogue: weighted scatter-add into output
#pragma unroll
    for (int im = 0; im < 2; im++)
#pragma unroll
        for (int in = 0; in < 4; in++) {
            int rb = wm * 32 + im * 16 + g;
            int nb = wn * 32 + in * 8 + q * 2;
#pragma unroll
            for (int h = 0; h < 2; h++) {
                int r = rb + h * 8;
                int gr = m0 + r;
                if (gr < mcnt) {
                    float wt = s_w[r];
                    float* op = out + (size_t)s_tok[r] * DD + d0 + nb;
                    atomicAdd(op + 0, acc[im][in][h * 2] * wt);
                    atomicAdd(op + 1, acc[im][in][h * 2 + 1] * wt);
                }
            }
        }
}

// ---------------- launcher ----------------
extern "C" void kernel_launch(void* const* d_in, const int* in_sizes, int n_in,
                              void* d_out, int out_size) {
    const float* x  = (const float*)d_in[0];
    const float* rw = (const float*)d_in[1];
    const float* gw = (const float*)d_in[2];
    const float* uw = (const float*)d_in[3];
    const float* dw = (const float*)d_in[4];
    float* out = (float*)d_out;

    cudaFuncSetAttribute(gemm1_kernel, cudaFuncAttributeMaxDynamicSharedMemorySize, NSTG * G1_STG);
    cudaFuncSetAttribute(gemm2_kernel, cudaFuncAttributeMaxDynamicSharedMemorySize, NSTG * G2_STG);

    prep_kernel<<<dim3(32, 32, 49), dim3(32, 8)>>>(x, gw, uw, dw);               // idx 0
    router_kernel<<<TT / 8, 256>>>(x, rw, out);                                  // idx 1
    scan_kernel<<<1, 512>>>();                                                   // idx 2
    gemm1_kernel<<<dim3(HH / 64, CBUF / BM, EE), 256, NSTG * G1_STG>>>();        // idx 3
    gemm2_kernel<<<dim3(DD / 64, CBUF / BM, EE), 256, NSTG * G2_STG>>>(out);     // idx 4
}